// round 12
// baseline (speedup 1.0000x reference)
#include <cuda_runtime.h>
#include <math.h>

// Scattering third-order via Parseval identity (corrected weighting):
//   out[b,i,j] = (1/MN^2) * sum_k F_j[k]^2 * Re( conj(X[b,k]) * XA_i[b,k] )
// where X = fft2(x), XA_i = fft2(abs_eps(ifft2(F_i * X))).
// Only 2*(1 + 32*2) 2D FFTs needed; pair dim becomes 672 dot products.

#define MDIM   128
#define MN     16384
#define NF     33      // filters (32 bandpass + 1 lowpass)
#define NFI    32      // first-order (bandpass only) count
#define NPAIR  672
#define BATCH  2
#define TS     129     // padded smem row stride in float2 (2-way conflict on row pass)
#define EPSV   1e-6f

// Scratch (static device arrays: allowed; runtime allocation is not)
__device__ float2 g_X[BATCH][MN];          // fft2(x)
__device__ float  g_H[BATCH][NFI][MN];     // Re(conj(X) * XA_i)

// ---------------------------------------------------------------------------
// Serial in-place radix-2 DIT FFT of 128 complex points at given smem stride.
// tw[k] = (cos(2*pi*k/128), sin(2*pi*k/128)), k=0..63.
// dir = -1 forward DFT (numpy fft), +1 inverse DFT (unnormalized).
// ---------------------------------------------------------------------------
__device__ __forceinline__ void fft_line(float2* a, int stride,
                                         const float2* __restrict__ tw, float dir) {
    // bit-reverse permutation (7 bits)
    #pragma unroll 1
    for (int i = 1; i < 128; ++i) {
        int j = (int)(__brev((unsigned)i) >> 25);
        if (j > i) {
            float2 t = a[i * stride];
            a[i * stride] = a[j * stride];
            a[j * stride] = t;
        }
    }
    #pragma unroll 1
    for (int len = 2; len <= 128; len <<= 1) {
        const int half  = len >> 1;
        const int tstep = 128 / len;
        for (int i = 0; i < 128; i += len) {
            #pragma unroll 4
            for (int k = 0; k < half; ++k) {
                float2 w = tw[k * tstep];
                float wr = w.x;
                float wi = dir * w.y;
                float2 u = a[(i + k) * stride];
                float2 v = a[(i + k + half) * stride];
                float tr = v.x * wr - v.y * wi;
                float ti = v.x * wi + v.y * wr;
                a[(i + k) * stride]        = make_float2(u.x + tr, u.y + ti);
                a[(i + k + half) * stride] = make_float2(u.x - tr, u.y - ti);
            }
        }
    }
}

// Full 2D FFT on a 128x128 tile in smem (padded stride TS). 128 threads.
__device__ __forceinline__ void fft2d(float2* tile, const float2* __restrict__ tw,
                                      float dir) {
    const int t = threadIdx.x;
    fft_line(tile + t * TS, 1, tw, dir);   // row t
    __syncthreads();
    fft_line(tile + t, TS, tw, dir);       // col t  (conflict-free)
    __syncthreads();
}

__device__ __forceinline__ void build_twiddles(float2* tw) {
    const int t = threadIdx.x;
    if (t < 64) {
        float s, c;
        sincospif((float)t / 64.f, &s, &c);   // angle = 2*pi*t/128
        tw[t] = make_float2(c, s);
    }
    __syncthreads();
}

// ---------------------------------------------------------------------------
// Kernel 1: X[b] = fft2(x[b]).  grid = BATCH, block = 128.
// ---------------------------------------------------------------------------
__global__ __launch_bounds__(128) void k_fft_x(const float* __restrict__ x) {
    extern __shared__ float2 sm[];
    float2* tile = sm;
    float2* tw   = sm + MDIM * TS;
    const int t = threadIdx.x;
    const int b = blockIdx.x;

    build_twiddles(tw);

    const float* xb = x + b * MN;
    #pragma unroll 4
    for (int r = 0; r < MDIM; ++r)
        tile[r * TS + t] = make_float2(xb[r * MDIM + t], 0.f);
    __syncthreads();

    fft2d(tile, tw, -1.f);

    #pragma unroll 4
    for (int r = 0; r < MDIM; ++r)
        g_X[b][r * MDIM + t] = tile[r * TS + t];
}

// ---------------------------------------------------------------------------
// Kernel 2: per (b, i):  xf = ifft2(F_i * X[b]); xa = abs_eps(xf);
//           XA = fft2(xa);  H[b,i,k] = Re( conj(X[b,k]) * XA[k] ).
// grid = BATCH*NFI, block = 128.
// ---------------------------------------------------------------------------
__global__ __launch_bounds__(128) void k_main(const float* __restrict__ F) {
    extern __shared__ float2 sm[];
    float2* tile = sm;
    float2* tw   = sm + MDIM * TS;
    const int t = threadIdx.x;
    const int b = blockIdx.x / NFI;
    const int i = blockIdx.x % NFI;

    build_twiddles(tw);

    const float* __restrict__ Fi = F + i * MN;
    #pragma unroll 4
    for (int r = 0; r < MDIM; ++r) {
        const int k = r * MDIM + t;
        const float  f  = Fi[k];
        const float2 xv = g_X[b][k];
        tile[r * TS + t] = make_float2(f * xv.x, f * xv.y);
    }
    __syncthreads();

    fft2d(tile, tw, +1.f);                 // inverse DFT, unnormalized

    const float sc = 1.f / (float)MN;      // ifft2 normalization
    #pragma unroll 4
    for (int r = 0; r < MDIM; ++r) {
        float2 z = tile[r * TS + t];
        float re = z.x * sc, im = z.y * sc;
        tile[r * TS + t] = make_float2(sqrtf(re * re + im * im + EPSV), 0.f);
    }
    __syncthreads();

    fft2d(tile, tw, -1.f);                 // forward DFT -> XA_i

    float* __restrict__ Hrow = g_H[b][i];
    #pragma unroll 4
    for (int r = 0; r < MDIM; ++r) {
        const int k = r * MDIM + t;
        const float2 xa = tile[r * TS + t];
        const float2 xv = g_X[b][k];
        // Re(conj(X) * XA) = X.re*XA.re + X.im*XA.im   (NO filter factor here)
        Hrow[k] = xa.x * xv.x + xa.y * xv.y;
    }
}

// ---------------------------------------------------------------------------
// Kernel 3: out[b,p] = (1/MN^2) * sum_k H[b, i0(p), k] * F[i1(p), k]^2
// Pair decode reproduces indices_third_order(J=4, L=8) ordering.
// grid = (NPAIR, BATCH), block = 256.
// ---------------------------------------------------------------------------
__global__ __launch_bounds__(256) void k_reduce(const float* __restrict__ F,
                                               float* __restrict__ out) {
    const int p = blockIdx.x;
    const int b = blockIdx.y;

    // decode (i0, i1)
    int rem = p, i0 = 0, i1 = 0;
    bool done = false;
    #pragma unroll 1
    for (int j1 = 0; j1 < 4 && !done; ++j1) {
        const int n = (4 - j1) * 8 + 1;    // pairs per (j1, l1)
        #pragma unroll 1
        for (int l1 = 0; l1 < 8 && !done; ++l1) {
            if (rem < n) {
                i0 = j1 * 8 + l1;
                if (rem == n - 1) i1 = 32;                       // lowpass last
                else              i1 = (j1 + rem / 8) * 8 + (rem % 8);
                done = true;
            } else {
                rem -= n;
            }
        }
    }

    const float* __restrict__ h = g_H[b][i0];
    const float* __restrict__ f = F + i1 * MN;

    float s = 0.f;
    for (int k = threadIdx.x; k < MN; k += 256) {
        float fv = f[k];
        s += h[k] * (fv * fv);             // weight = F_j^2
    }

    // block reduce (8 warps)
    __shared__ float wsum[8];
    #pragma unroll
    for (int o = 16; o; o >>= 1) s += __shfl_xor_sync(0xffffffffu, s, o);
    if ((threadIdx.x & 31) == 0) wsum[threadIdx.x >> 5] = s;
    __syncthreads();
    if (threadIdx.x < 32) {
        float v = (threadIdx.x < 8) ? wsum[threadIdx.x] : 0.f;
        #pragma unroll
        for (int o = 4; o; o >>= 1) v += __shfl_xor_sync(0xffffffffu, v, o);
        if (threadIdx.x == 0)
            out[b * NPAIR + p] = v * (1.f / ((float)MN * (float)MN));
    }
}

// ---------------------------------------------------------------------------
extern "C" void kernel_launch(void* const* d_in, const int* in_sizes, int n_in,
                              void* d_out, int out_size) {
    const float* x = (const float*)d_in[0];   // (B,1,128,128) float32
    const float* F = (const float*)d_in[1];   // (1,33,128,128) float32
    float* out = (float*)d_out;               // (B,672) float32

    const int SMEM = (MDIM * TS + 64) * (int)sizeof(float2);  // tile + twiddles

    cudaFuncSetAttribute(k_fft_x, cudaFuncAttributeMaxDynamicSharedMemorySize, SMEM);
    cudaFuncSetAttribute(k_main,  cudaFuncAttributeMaxDynamicSharedMemorySize, SMEM);

    k_fft_x<<<BATCH, 128, SMEM>>>(x);
    k_main<<<BATCH * NFI, 128, SMEM>>>(F);
    k_reduce<<<dim3(NPAIR, BATCH), 256>>>(F, out);
}

// round 13
// speedup vs baseline: 2.2387x; 2.2387x over previous
#include <cuda_runtime.h>
#include <math.h>

// Scattering third-order via Parseval identity:
//   out[b,i,j] = (1/MN^2) * sum_k F_j[k]^2 * Re( conj(X[b,k]) * XA_i[b,k] )
// X = fft2(x), XA_i = fft2(abs_eps(ifft2(F_i * X))).
//
// FFT engine: 4 threads per 128-pt line, 32 complex elements in registers per
// thread (contiguous block). Stages len=8..128 in position space: spans 64,32
// are cross-thread (shfl_xor 2 / 1), spans <=16 thread-local.
// Inverse uses DIF (natural -> bitrev), forward uses DIT (bitrev -> natural),
// so the spatial domain stays bit-reversed and no permutations are needed in
// the main kernel (abs is pointwise).

#define MDIM   128
#define MN     16384
#define NFI    32
#define NPAIR  672
#define BATCH  2
#define EPSV   1e-6f

__device__ float2 g_X[BATCH][MN];          // fft2(x), natural order
__device__ float  g_H[BATCH][NFI][MN];     // Re(conj(X) * XA_i)

// ---------------------------------------------------------------------------
__device__ __forceinline__ float2 shflx(float2 a, int m) {
    a.x = __shfl_xor_sync(0xffffffffu, a.x, m);
    a.y = __shfl_xor_sync(0xffffffffu, a.y, m);
    return a;
}

// Conflict-free smem layout (float2 index) for logical (row, col):
// interleaved column permutation XOR row-derived nibble; row stride 128 (0 mod 16).
__device__ __forceinline__ int smaddr(int row, int col) {
    int pc = ((col & 31) << 2) | (col >> 5);
    int s  = ((row >> 5) & 3) | ((row & 3) << 2);
    return (row << 7) + (pc ^ s);
}

template<int SGN>  // SGN = -1 forward (numpy fft), +1 inverse (unnormalized)
__device__ __forceinline__ float2 cmulw(float2 a, float2 w) {
    float wi = (float)SGN * w.y;
    return make_float2(a.x * w.x - a.y * wi, a.x * wi + a.y * w.x);
}

template<int SGN>
__device__ __forceinline__ void bfly_dif(float2& a, float2& b, float2 w) {
    float ur = a.x - b.x, ui = a.y - b.y;
    a.x += b.x; a.y += b.y;
    float wi = (float)SGN * w.y;
    b.x = ur * w.x - ui * wi;
    b.y = ur * wi + ui * w.x;
}

template<int SGN>
__device__ __forceinline__ void bfly_dit(float2& a, float2& b, float2 w) {
    float wi = (float)SGN * w.y;
    float tr = b.x * w.x - b.y * wi;
    float ti = b.x * wi + b.y * w.x;
    b.x = a.x - tr; b.y = a.y - ti;
    a.x += tr; a.y += ti;
}

// DIF: natural input -> bit-reversed output. Thread t owns positions 32t+j.
template<int SGN>
__device__ __forceinline__ void dif_line(float2 v[32], int t, const float2* __restrict__ tw) {
    // len=128 (span 64, cross t^2), twiddle m = 32*(t&1)+j
    {
        const float2* twm = tw + ((t & 1) << 5);
        const bool hi = (t >= 2);
        #pragma unroll
        for (int j = 0; j < 32; ++j) {
            float2 a = v[j];
            float2 p = shflx(a, 2);
            if (!hi) { v[j] = make_float2(a.x + p.x, a.y + p.y); }
            else     { v[j] = cmulw<SGN>(make_float2(p.x - a.x, p.y - a.y), twm[j]); }
        }
    }
    // len=64 (span 32, cross t^1), m = 2j
    {
        const bool hi = (t & 1);
        #pragma unroll
        for (int j = 0; j < 32; ++j) {
            float2 a = v[j];
            float2 p = shflx(a, 1);
            if (!hi) { v[j] = make_float2(a.x + p.x, a.y + p.y); }
            else     { v[j] = cmulw<SGN>(make_float2(p.x - a.x, p.y - a.y), tw[2 * j]); }
        }
    }
    // len=32: pairs (j, j+16), m = 4j
    #pragma unroll
    for (int j = 0; j < 16; ++j) bfly_dif<SGN>(v[j], v[j + 16], tw[4 * j]);
    // len=16
    #pragma unroll
    for (int b = 0; b < 32; b += 16)
        #pragma unroll
        for (int j = 0; j < 8; ++j) bfly_dif<SGN>(v[b + j], v[b + j + 8], tw[8 * j]);
    // len=8
    #pragma unroll
    for (int b = 0; b < 32; b += 8)
        #pragma unroll
        for (int j = 0; j < 4; ++j) bfly_dif<SGN>(v[b + j], v[b + j + 4], tw[16 * j]);
    // len=4
    #pragma unroll
    for (int b = 0; b < 32; b += 4)
        #pragma unroll
        for (int j = 0; j < 2; ++j) bfly_dif<SGN>(v[b + j], v[b + j + 2], tw[32 * j]);
    // len=2 (w = 1)
    #pragma unroll
    for (int b = 0; b < 32; b += 2) {
        float2 u = v[b], w2 = v[b + 1];
        v[b]     = make_float2(u.x + w2.x, u.y + w2.y);
        v[b + 1] = make_float2(u.x - w2.x, u.y - w2.y);
    }
}

// DIT: bit-reversed input -> natural output.
template<int SGN>
__device__ __forceinline__ void dit_line(float2 v[32], int t, const float2* __restrict__ tw) {
    // len=2 (w = 1)
    #pragma unroll
    for (int b = 0; b < 32; b += 2) {
        float2 u = v[b], w2 = v[b + 1];
        v[b]     = make_float2(u.x + w2.x, u.y + w2.y);
        v[b + 1] = make_float2(u.x - w2.x, u.y - w2.y);
    }
    // len=4
    #pragma unroll
    for (int b = 0; b < 32; b += 4)
        #pragma unroll
        for (int j = 0; j < 2; ++j) bfly_dit<SGN>(v[b + j], v[b + j + 2], tw[32 * j]);
    // len=8
    #pragma unroll
    for (int b = 0; b < 32; b += 8)
        #pragma unroll
        for (int j = 0; j < 4; ++j) bfly_dit<SGN>(v[b + j], v[b + j + 4], tw[16 * j]);
    // len=16
    #pragma unroll
    for (int b = 0; b < 32; b += 16)
        #pragma unroll
        for (int j = 0; j < 8; ++j) bfly_dit<SGN>(v[b + j], v[b + j + 8], tw[8 * j]);
    // len=32
    #pragma unroll
    for (int j = 0; j < 16; ++j) bfly_dit<SGN>(v[j], v[j + 16], tw[4 * j]);
    // len=64 (cross t^1), m = 2j: high thread scales own value, then exchange
    {
        const bool hi = (t & 1);
        #pragma unroll
        for (int j = 0; j < 32; ++j) {
            float2 a = v[j];
            if (hi) a = cmulw<SGN>(a, tw[2 * j]);
            float2 p = shflx(a, 1);
            v[j] = hi ? make_float2(p.x - a.x, p.y - a.y)
                      : make_float2(a.x + p.x, a.y + p.y);
        }
    }
    // len=128 (cross t^2), m = 32*(t&1)+j
    {
        const float2* twm = tw + ((t & 1) << 5);
        const bool hi = (t >= 2);
        #pragma unroll
        for (int j = 0; j < 32; ++j) {
            float2 a = v[j];
            if (hi) a = cmulw<SGN>(a, twm[j]);
            float2 p = shflx(a, 2);
            v[j] = hi ? make_float2(p.x - a.x, p.y - a.y)
                      : make_float2(a.x + p.x, a.y + p.y);
        }
    }
}

__device__ __forceinline__ void build_tw(float2* tw, int tid) {
    if (tid < 64) {
        float s, c;
        sincospif((float)tid / 64.f, &s, &c);   // e^{+2*pi*i*tid/128}
        tw[tid] = make_float2(c, s);
    }
}

// ---------------------------------------------------------------------------
// Kernel 1: X[b] = fft2(x[b]) (natural order out via bitrev scatter).
// grid = BATCH, block = 512.
// ---------------------------------------------------------------------------
__global__ __launch_bounds__(512, 1) void k_fft_x(const float* __restrict__ x) {
    extern __shared__ float2 sm[];
    float2* tile = sm;
    float2* tw   = sm + MDIM * MDIM;
    const int tid  = threadIdx.x;
    const int line = tid >> 2, t = tid & 3;
    const int b = blockIdx.x;

    build_tw(tw, tid);
    __syncthreads();

    float2 v[32];
    const float* xb = x + b * MN + line * MDIM + 32 * t;
    #pragma unroll
    for (int j = 0; j < 32; ++j) v[j] = make_float2(xb[j], 0.f);

    dif_line<-1>(v, t, tw);                          // forward over cols
    #pragma unroll
    for (int j = 0; j < 32; ++j) tile[smaddr(line, 32 * t + j)] = v[j];
    __syncthreads();
    #pragma unroll
    for (int j = 0; j < 32; ++j) v[j] = tile[smaddr(32 * t + j, line)];
    dif_line<-1>(v, t, tw);                          // forward over rows

    // value at (pos p=32t+j, tile col=line) is X[brev(p)][brev(line)]
    const int bc = (int)(__brev((unsigned)line) >> 25);
    #pragma unroll
    for (int j = 0; j < 32; ++j) {
        int br = (int)(__brev((unsigned)(32 * t + j)) >> 25);
        g_X[b][br * MDIM + bc] = v[j];
    }
}

// ---------------------------------------------------------------------------
// Kernel 2: per (b,i): H = Re(conj(X) * fft2(abs_eps(ifft2(F_i*X)))).
// grid = BATCH*NFI, block = 512.
// ---------------------------------------------------------------------------
__global__ __launch_bounds__(512, 1) void k_main(const float* __restrict__ F) {
    extern __shared__ float2 sm[];
    float2* tile = sm;
    float2* tw   = sm + MDIM * MDIM;
    const int tid  = threadIdx.x;
    const int line = tid >> 2, t = tid & 3;
    const int b = blockIdx.x >> 5;
    const int i = blockIdx.x & 31;

    build_tw(tw, tid);
    __syncthreads();

    const int base = line * MDIM + 32 * t;
    const float* __restrict__ Fi = F + i * MN + base;
    float2 v[32];
    #pragma unroll
    for (int j = 0; j < 32; ++j) {
        float  f  = Fi[j];
        float2 xv = g_X[b][base + j];
        v[j] = make_float2(f * xv.x, f * xv.y);
    }

    dif_line<1>(v, t, tw);                           // inverse over cols
    #pragma unroll
    for (int j = 0; j < 32; ++j) tile[smaddr(line, 32 * t + j)] = v[j];
    __syncthreads();
    #pragma unroll
    for (int j = 0; j < 32; ++j) v[j] = tile[smaddr(32 * t + j, line)];
    dif_line<1>(v, t, tw);                           // inverse over rows

    // spatial (doubly bit-reversed layout, order-agnostic), normalize + abs
    const float sc = 1.f / (float)MN;
    #pragma unroll
    for (int j = 0; j < 32; ++j) {
        float re = v[j].x * sc, im = v[j].y * sc;
        v[j] = make_float2(sqrtf(re * re + im * im + EPSV), 0.f);
    }

    dit_line<-1>(v, t, tw);                          // forward over rows (in regs!)
    __syncthreads();                                 // all col-loads done before overwrite
    #pragma unroll
    for (int j = 0; j < 32; ++j) tile[smaddr(32 * t + j, line)] = v[j];
    __syncthreads();
    #pragma unroll
    for (int j = 0; j < 32; ++j) v[j] = tile[smaddr(line, 32 * t + j)];
    dit_line<-1>(v, t, tw);                          // forward over cols -> XA natural

    float* __restrict__ Hrow = g_H[b][i] + base;
    #pragma unroll
    for (int j = 0; j < 32; ++j) {
        float2 xv = g_X[b][base + j];
        Hrow[j] = v[j].x * xv.x + v[j].y * xv.y;     // Re(conj(X)*XA)
    }
}

// ---------------------------------------------------------------------------
// Kernel 3: out[b,p] = (1/MN^2) * sum_k H[b,i0(p),k] * F[i1(p),k]^2
// grid = (NPAIR, BATCH), block = 256. float4 vectorized.
// ---------------------------------------------------------------------------
__global__ __launch_bounds__(256) void k_reduce(const float* __restrict__ F,
                                               float* __restrict__ out) {
    const int p = blockIdx.x;
    const int b = blockIdx.y;

    int rem = p, i0 = 0, i1 = 0;
    bool done = false;
    #pragma unroll 1
    for (int j1 = 0; j1 < 4 && !done; ++j1) {
        const int n = (4 - j1) * 8 + 1;
        #pragma unroll 1
        for (int l1 = 0; l1 < 8 && !done; ++l1) {
            if (rem < n) {
                i0 = j1 * 8 + l1;
                if (rem == n - 1) i1 = 32;
                else              i1 = (j1 + rem / 8) * 8 + (rem % 8);
                done = true;
            } else rem -= n;
        }
    }

    const float4* __restrict__ h4 = (const float4*)g_H[b][i0];
    const float4* __restrict__ f4 = (const float4*)(F + i1 * MN);

    float s = 0.f;
    #pragma unroll 4
    for (int k = threadIdx.x; k < MN / 4; k += 256) {
        float4 hv = h4[k], fv = f4[k];
        s += hv.x * (fv.x * fv.x) + hv.y * (fv.y * fv.y)
           + hv.z * (fv.z * fv.z) + hv.w * (fv.w * fv.w);
    }

    __shared__ float wsum[8];
    #pragma unroll
    for (int o = 16; o; o >>= 1) s += __shfl_xor_sync(0xffffffffu, s, o);
    if ((threadIdx.x & 31) == 0) wsum[threadIdx.x >> 5] = s;
    __syncthreads();
    if (threadIdx.x < 32) {
        float vv = (threadIdx.x < 8) ? wsum[threadIdx.x] : 0.f;
        #pragma unroll
        for (int o = 4; o; o >>= 1) vv += __shfl_xor_sync(0xffffffffu, vv, o);
        if (threadIdx.x == 0)
            out[b * NPAIR + p] = vv * (1.f / ((float)MN * (float)MN));
    }
}

// ---------------------------------------------------------------------------
extern "C" void kernel_launch(void* const* d_in, const int* in_sizes, int n_in,
                              void* d_out, int out_size) {
    const float* x = (const float*)d_in[0];   // (B,1,128,128) float32
    const float* F = (const float*)d_in[1];   // (1,33,128,128) float32
    float* out = (float*)d_out;               // (B,672) float32

    const int SMEM = (MDIM * MDIM + 64) * (int)sizeof(float2);  // tile + twiddles

    cudaFuncSetAttribute(k_fft_x, cudaFuncAttributeMaxDynamicSharedMemorySize, SMEM);
    cudaFuncSetAttribute(k_main,  cudaFuncAttributeMaxDynamicSharedMemorySize, SMEM);

    k_fft_x<<<BATCH, 512, SMEM>>>(x);
    k_main<<<BATCH * NFI, 512, SMEM>>>(F);
    k_reduce<<<dim3(NPAIR, BATCH), 256>>>(F, out);
}